// round 16
// baseline (speedup 1.0000x reference)
#include <cuda_runtime.h>
#include <cuda_bf16.h>
#include <stdint.h>

// Problem constants (fixed by reference: B=16, NT=4096, D=512, V=2545)
#define B_  16
#define NT_ 4096
#define D_  512
#define V_  2545
#define NV  (V_ + 1)                 // 2546 token slots (emb indices 0..2545)
#define D_VEC (D_ / 4)               // 128 float4 per embedding row
#define NROWS (B_ * NT_)             // 65536 output rows
#define NPREP 128                    // map blocks (8 chunks x 16 batches)
#define CHUNK (NT_ / 8)              // 512 positions per map chunk

// Scratch (device allocations forbidden -> __device__ globals)
__device__ int      g_len[B_];
__device__ int      g_is64;
__device__ int      g_tok[NROWS];     // emb index per output row, or -1 => zeros
__device__ int      g_hist[NV];       // per-token row count (rebuilt every launch)
__device__ int      g_cursor[NV];     // scatter cursors (rebuilt every launch)
__device__ unsigned g_perm[NROWS];    // token-grouped order: ((tok+1)<<16) | row

// ---------------------------------------------------------------------------
// K1: count + probe + zero histogram. 16 blocks x 512 threads.
// ---------------------------------------------------------------------------
__global__ void __launch_bounds__(512)
count_kernel(const int* __restrict__ t32) {
    const int b   = blockIdx.x;
    const int tid = threadIdx.x;

    // zero g_hist (each slot written exactly once across the grid)
    const int gid = b * 512 + tid;
    if (gid < NV) g_hist[gid] = 0;

    // dtype probe
    int bad = 0;
    if (tid < 256) {
        const int lo = t32[2 * tid];
        const int hi = t32[2 * tid + 1];
        const int want_hi = (lo < 0) ? -1 : 0;
        if (hi != want_hi || lo < -1 || lo >= V_) bad = 1;
    }
    const int is64 = __syncthreads_or(bad) ? 0 : 1;
    const int stride = is64 ? 2 : 1;
    const int* row = t32 + (size_t)b * NT_ * stride;

    int cnt = 0;
    #pragma unroll
    for (int i = tid; i < NT_; i += 512)
        cnt += (row[(size_t)i * stride] >= 0);
    #pragma unroll
    for (int off = 16; off > 0; off >>= 1)
        cnt += __shfl_down_sync(0xFFFFFFFFu, cnt, off);

    __shared__ int s_part[16];
    if ((tid & 31) == 0) s_part[tid >> 5] = cnt;
    __syncthreads();
    if (tid == 0) {
        int total = 0;
        for (int w = 0; w < 16; ++w) total += s_part[w];
        g_len[b] = total;
        if (b == 0) g_is64 = is64;
    }
}

// ---------------------------------------------------------------------------
// K2: stretch mapping -> g_tok, plus token histogram. 128 blocks x 512.
// ---------------------------------------------------------------------------
__global__ void __launch_bounds__(512)
map_hist_kernel(const int* __restrict__ t32) {
    const int b     = blockIdx.x >> 3;
    const int chunk = blockIdx.x & 7;
    const int tid   = threadIdx.x;

    const int L = g_len[b];
    const int stride = g_is64 ? 2 : 1;
    const int* row = t32 + (size_t)b * NT_ * stride;

    const int p = chunk * CHUNK + tid;
    int tok;
    if (L <= 0) {
        tok = -1;                                  // impossible per reference
    } else {
        const unsigned base = (unsigned)NT_ / (unsigned)L;
        const unsigned rem  = (unsigned)NT_ % (unsigned)L;
        const unsigned boundary = ((unsigned)L - rem) * base;
        unsigned j;
        if ((unsigned)p < boundary) j = (unsigned)p / base;
        else                        j = ((unsigned)L - rem) + ((unsigned)p - boundary) / (base + 1);
        int t = row[(size_t)j * stride] + 1;       // [1, V] for valid prefix
        tok = min(max(t, 0), V_);                  // hard safety clamp
    }
    g_tok[b * NT_ + p] = tok;
    atomicAdd(&g_hist[max(tok, 0)], 1);
}

// ---------------------------------------------------------------------------
// K3: exclusive prefix sum of g_hist -> g_cursor. 1 block x 1024 threads,
// 4 slots per thread (covers 4096 >= 2546). Classic 3-level scan.
// ---------------------------------------------------------------------------
__global__ void __launch_bounds__(1024)
scan_kernel() {
    const int tid  = threadIdx.x;
    const int lane = tid & 31;
    const int wid  = tid >> 5;
    const int base = tid * 4;

    int v[4];
    #pragma unroll
    for (int i = 0; i < 4; ++i)
        v[i] = (base + i < NV) ? g_hist[base + i] : 0;

    const int e0 = 0;
    const int e1 = v[0];
    const int e2 = v[0] + v[1];
    const int e3 = v[0] + v[1] + v[2];
    const int tot = e3 + v[3];

    // warp-inclusive scan of per-thread totals
    int inc = tot;
    #pragma unroll
    for (int o = 1; o < 32; o <<= 1) {
        int n = __shfl_up_sync(0xFFFFFFFFu, inc, o);
        if (lane >= o) inc += n;
    }
    const int wexcl = inc - tot;

    __shared__ int wtot[32];
    if (lane == 31) wtot[wid] = inc;
    __syncthreads();
    if (wid == 0) {
        int t = wtot[lane];
        int i2 = t;
        #pragma unroll
        for (int o = 1; o < 32; o <<= 1) {
            int n = __shfl_up_sync(0xFFFFFFFFu, i2, o);
            if (lane >= o) i2 += n;
        }
        wtot[lane] = i2 - t;   // exclusive warp offsets
    }
    __syncthreads();

    const int texcl = wtot[wid] + wexcl;
    if (base + 0 < NV) g_cursor[base + 0] = texcl + e0;
    if (base + 1 < NV) g_cursor[base + 1] = texcl + e1;
    if (base + 2 < NV) g_cursor[base + 2] = texcl + e2;
    if (base + 3 < NV) g_cursor[base + 3] = texcl + e3;
}

// ---------------------------------------------------------------------------
// K4: scatter rows into token-grouped order. 128 blocks x 512 threads.
// Every g_perm slot is written exactly once (sum of hist == NROWS); order
// within a token is atomic-race-dependent but OUTPUT-irrelevant (all rows of
// a token receive identical data) -> deterministic result.
// ---------------------------------------------------------------------------
__global__ void __launch_bounds__(512)
scatter_kernel() {
    const int p = blockIdx.x * 512 + threadIdx.x;    // 65536 threads total
    const int tok = g_tok[p];
    const int slot = max(tok, 0);
    const int pos = atomicAdd(&g_cursor[slot], 1);
    g_perm[pos] = ((unsigned)(tok + 1) << 16) | (unsigned)p;   // 0 in hi => zero-fill
}

// ---------------------------------------------------------------------------
// K5: token-grouped gather-copy. 4096 blocks x 256 threads = 2 groups of 128
// lanes; each group handles 8 CONSECUTIVE perm entries (~26 rows/token mean
// run length => most groups need ONE emb load). Loads dedup in registers;
// cross-group reuse hits L1/L2. Stores: 2 KB-contiguous per row (coalesced),
// row order scattered — harmless.
// ---------------------------------------------------------------------------
__global__ void __launch_bounds__(256)
grouped_copy_kernel(const float4* __restrict__ emb,
                    float4* __restrict__ out) {
    const int lane = threadIdx.x & 127;
    const int sub  = threadIdx.x >> 7;               // 0 or 1
    const int eBase = blockIdx.x * 16 + sub * 8;     // 8 consecutive perm entries

    unsigned e[8];
    #pragma unroll
    for (int k = 0; k < 8; ++k)
        e[k] = g_perm[eBase + k];

    float4 v[8];
    #pragma unroll
    for (int k = 0; k < 8; ++k) {
        const unsigned idx = e[k] >> 16;             // tok+1, or 0 => zeros
        if (k > 0 && idx == (e[k - 1] >> 16)) {
            v[k] = v[k - 1];
        } else if (idx != 0) {
            v[k] = __ldg(emb + (size_t)(idx - 1) * D_VEC + lane);
        } else {
            v[k] = make_float4(0.f, 0.f, 0.f, 0.f);
        }
    }

    #pragma unroll
    for (int k = 0; k < 8; ++k)
        __stcs(out + (size_t)(e[k] & 0xFFFFu) * D_VEC + lane, v[k]);
}

// ---------------------------------------------------------------------------
// Launch: 5 kernels, all graph-capturable, allocation-free.
// ---------------------------------------------------------------------------
extern "C" void kernel_launch(void* const* d_in, const int* in_sizes, int n_in,
                              void* d_out, int out_size) {
    const int*   text = nullptr;
    const float* emb  = nullptr;
    for (int i = 0; i < n_in; ++i) {
        if (in_sizes[i] == NROWS || in_sizes[i] == 2 * NROWS)
            text = (const int*)d_in[i];
        else if (in_sizes[i] == (V_ + 1) * D_)
            emb = (const float*)d_in[i];
    }

    count_kernel<<<B_, 512>>>(text);
    map_hist_kernel<<<NPREP, 512>>>(text);
    scan_kernel<<<1, 1024>>>();
    scatter_kernel<<<NROWS / 512, 512>>>();
    grouped_copy_kernel<<<NROWS / 16, 256>>>((const float4*)emb, (float4*)d_out);
    (void)out_size;
}

// round 17
// speedup vs baseline: 1.4094x; 1.4094x over previous
#include <cuda_runtime.h>
#include <cuda_bf16.h>
#include <stdint.h>

// Problem constants (fixed by reference: B=16, NT=4096, D=512, V=2545)
#define B_  16
#define NT_ 4096
#define D_  512
#define V_  2545
#define D_VEC (D_ / 4)               // 128 float4 per embedding row
#define NROWS (B_ * NT_)             // 65536 output rows
#define NPREP 128                    // prep blocks (8 chunks x 16 batches)
#define CHUNK (NT_ / 8)              // 512 positions per prep chunk

// Hybrid split: blocks [0, STG_TILES) use the STG path (8 rows each);
// blocks [STG_TILES, 8192) use the TMA bulk-store path (8 rows each).
#define TOTAL_TILES (NROWS / 8)      // 8192
#define STG_TILES   4928             // ~60% of rows on the LSU/STG drain
#define TILE_F4     (8 * D_VEC)      // 1024 float4 = 16 KB per tile
#define TILE_BYTES  (TILE_F4 * 16)   // 16384

// Scratch (device allocations forbidden -> __device__ global)
__device__ int g_tok[NROWS];   // source token per output row (+1 applied), or -1 => zeros

// ---------------------------------------------------------------------------
// Prep kernel (proven R7 config): 128 blocks x 512 threads.
//  (a) dtype probe (int64 little-endian word-pairs vs int32);
//  (b) valid-token count L_b;
//  (c) stretch mapping for this block's 512 positions -> g_tok.
// Ends with the PDL trigger so the copy kernel's launch/ramp overlaps our
// execution (proven safe in R9).
// ---------------------------------------------------------------------------
__global__ void __launch_bounds__(512)
prep_kernel(const int* __restrict__ t32) {
    const int b     = blockIdx.x >> 3;
    const int chunk = blockIdx.x & 7;
    const int tid   = threadIdx.x;

    int bad = 0;
    if (tid < 256) {
        const int lo = t32[2 * tid];
        const int hi = t32[2 * tid + 1];
        const int want_hi = (lo < 0) ? -1 : 0;
        if (hi != want_hi || lo < -1 || lo >= V_) bad = 1;
    }
    const int is64 = __syncthreads_or(bad) ? 0 : 1;
    const int stride = is64 ? 2 : 1;
    const int* row = t32 + (size_t)b * NT_ * stride;

    int cnt = 0;
    #pragma unroll
    for (int i = tid; i < NT_; i += 512)
        cnt += (row[(size_t)i * stride] >= 0);
    #pragma unroll
    for (int off = 16; off > 0; off >>= 1)
        cnt += __shfl_down_sync(0xFFFFFFFFu, cnt, off);

    __shared__ int s_part[16];
    if ((tid & 31) == 0) s_part[tid >> 5] = cnt;
    __syncthreads();
    __shared__ int s_L;
    if (tid == 0) {
        int total = 0;
        for (int w = 0; w < 16; ++w) total += s_part[w];
        s_L = total;
    }
    __syncthreads();
    const int L = s_L;

    const int p = chunk * CHUNK + tid;
    int* tok_row = g_tok + b * NT_;
    if (L <= 0) {
        tok_row[p] = -1;
    } else {
        const unsigned base = (unsigned)NT_ / (unsigned)L;
        const unsigned rem  = (unsigned)NT_ % (unsigned)L;
        const unsigned boundary = ((unsigned)L - rem) * base;
        unsigned j;
        if ((unsigned)p < boundary) j = (unsigned)p / base;
        else                        j = ((unsigned)L - rem) + ((unsigned)p - boundary) / (base + 1);
        int t = row[(size_t)j * stride] + 1;    // [1, V] for valid prefix
        tok_row[p] = min(max(t, 0), V_);        // hard safety clamp
    }

#if defined(__CUDA_ARCH__) && (__CUDA_ARCH__ >= 900)
    cudaTriggerProgrammaticLaunchCompletion();
#endif
}

// ---------------------------------------------------------------------------
// Hybrid embed kernel (best measured config, R14): 8192 blocks x 256 threads.
//  - Blocks [0, STG_TILES): R3/R7 gather-copy body — MLP=4 LDG.128 gathers +
//    4 STG.128 streaming stores (LSU drain).
//  - Blocks [STG_TILES, 8192): gather into SMEM, then ONE 16 KB
//    cp.async.bulk shared->global on the TMA pipe.
// Entry: HW PDL dependency wait (guarantees prep's g_tok is visible).
// ---------------------------------------------------------------------------
__global__ void __launch_bounds__(256)
hybrid_embed_kernel(const float4* __restrict__ emb,
                    float4* __restrict__ out) {
#if defined(__CUDA_ARCH__) && (__CUDA_ARCH__ >= 900)
    cudaGridDependencySynchronize();
#endif

    __shared__ alignas(128) float4 s_buf[TILE_F4];   // 16 KB (TMA path)

    const int tid = threadIdx.x;
    const int bid = blockIdx.x;

    if (bid < STG_TILES) {
        // ---------------- STG path ----------------
        const int lane = tid & 127;
        const int sub  = tid >> 7;              // 0 or 1
        const int rowBase = bid * 8 + sub;

        int tok[4];
        #pragma unroll
        for (int k = 0; k < 4; ++k)
            tok[k] = __ldg(&g_tok[rowBase + 2 * k]);

        float4 v[4];
        #pragma unroll
        for (int k = 0; k < 4; ++k) {
            if (tok[k] >= 0)
                v[k] = __ldg(emb + (size_t)tok[k] * D_VEC + lane);
            else
                v[k] = make_float4(0.f, 0.f, 0.f, 0.f);
        }

        #pragma unroll
        for (int k = 0; k < 4; ++k)
            __stcs(out + (size_t)(rowBase + 2 * k) * D_VEC + lane, v[k]);
    } else {
        // ---------------- TMA bulk-store path ----------------
        const int rowBase = bid * 8;            // 8 consecutive rows

        __shared__ int s_tok[8];
        if (tid < 8)
            s_tok[tid] = g_tok[rowBase + tid];
        __syncthreads();

        #pragma unroll
        for (int k = 0; k < 4; ++k) {
            const int idx  = tid + k * 256;
            const int r    = idx >> 7;
            const int lane = idx & 127;
            const int t    = s_tok[r];
            s_buf[idx] = (t >= 0) ? __ldg(emb + (size_t)t * D_VEC + lane)
                                  : make_float4(0.f, 0.f, 0.f, 0.f);
        }

        __syncthreads();
        asm volatile("fence.proxy.async.shared::cta;" ::: "memory");

        if (tid == 0) {
            uint32_t s_addr = (uint32_t)__cvta_generic_to_shared(s_buf);
            float4* gdst = out + (size_t)rowBase * D_VEC;
            asm volatile(
                "cp.async.bulk.global.shared::cta.bulk_group [%0], [%1], %2;"
                :: "l"(gdst), "r"(s_addr), "r"((unsigned)TILE_BYTES)
                : "memory");
            asm volatile("cp.async.bulk.commit_group;" ::: "memory");
            asm volatile("cp.async.bulk.wait_group 0;" ::: "memory");
        }
    }
}

// ---------------------------------------------------------------------------
// Launch: prep, then hybrid copy via PDL (programmatic stream serialization)
// so the copy's launch/ramp overlaps prep's execution. Both plain launches —
// graph-capturable, allocation-free.
// ---------------------------------------------------------------------------
extern "C" void kernel_launch(void* const* d_in, const int* in_sizes, int n_in,
                              void* d_out, int out_size) {
    const int*   text = nullptr;
    const float* emb  = nullptr;
    for (int i = 0; i < n_in; ++i) {
        if (in_sizes[i] == NROWS || in_sizes[i] == 2 * NROWS)
            text = (const int*)d_in[i];
        else if (in_sizes[i] == (V_ + 1) * D_)
            emb = (const float*)d_in[i];
    }

    prep_kernel<<<NPREP, 512>>>(text);

    cudaLaunchConfig_t cfg = {};
    cfg.gridDim  = dim3(TOTAL_TILES, 1, 1);
    cfg.blockDim = dim3(256, 1, 1);
    cfg.dynamicSmemBytes = 0;
    cfg.stream = 0;
    cudaLaunchAttribute attr[1];
    attr[0].id = cudaLaunchAttributeProgrammaticStreamSerialization;
    attr[0].val.programmaticStreamSerializationAllowed = 1;
    cfg.attrs = attr;
    cfg.numAttrs = 1;

    const float4* emb4 = (const float4*)emb;
    float4* out4 = (float4*)d_out;
    cudaError_t e = cudaLaunchKernelEx(&cfg, hybrid_embed_kernel, emb4, out4);
    if (e != cudaSuccess) {
        hybrid_embed_kernel<<<TOTAL_TILES, 256>>>(emb4, out4);
    }
    (void)out_size;
}